// round 8
// baseline (speedup 1.0000x reference)
#include <cuda_runtime.h>
#include <cuda_bf16.h>
#include <cstdint>

// Chamfer loss, B=8, N=M=4096, D=3, sm_103a.
// Round 8: single-wave residency. Same structure as round 7 (grid (16,8,8) =
// 1024 blocks x 256 threads, 4 query-groups x QPT=4, TSPLIT=4 target slices,
// FFMA2 inner loop: per paired record 2x LDS.128 + 12x FFMA2 + 8x FMNMX),
// but __launch_bounds__(256, 7) caps regs at 36 so 7 blocks fit per SM:
// 148 SMs x 7 = 1036 >= 1024 blocks -> one wave, no low-occupancy tail.

#define B_DIM   8
#define NPTS    4096
#define TPB     256
#define GSZ     64
#define NGRP    (TPB / GSZ)                 // 4
#define QPT     4
#define QPB     (GSZ * QPT)                 // 256 queries per block
#define TSPLIT  4
#define TILE    (NPTS / TSPLIT)             // 1024 targets per block
#define RECS    (TILE / 2)                  // 512 records
#define RPG     (RECS / NGRP)               // 128 records per group
#define QBLK    (NPTS / QPB)                // 16
#define NGROUPS (QBLK * B_DIM * 2)          // 256 merge groups
#define GRIDZ   (2 * TSPLIT)

__device__ float        g_min[NGROUPS * TSPLIT * QPB];
__device__ float        g_partials[NGROUPS];
__device__ unsigned int g_cnt1[NGROUPS];
__device__ unsigned int g_cnt2;

__device__ __forceinline__ unsigned long long pack2(float v) {
    unsigned long long r;
    asm("mov.b64 %0, {%1, %2};" : "=l"(r) : "f"(v), "f"(v));
    return r;
}

__global__ __launch_bounds__(TPB, 7) void chamfer_fused_kernel(
    const float* __restrict__ in_pts,
    const float* __restrict__ tg_pts,
    float* __restrict__ out)
{
    const int dir = blockIdx.z / TSPLIT;
    const int ts  = blockIdx.z % TSPLIT;
    const float* __restrict__ qset = dir ? tg_pts : in_pts;
    const float* __restrict__ tset = dir ? in_pts : tg_pts;
    const int b   = blockIdx.y;
    const int tid = threadIdx.x;
    const int g   = tid >> 6;
    const int lid = tid & 63;
    const int qbase = blockIdx.x * QPB;

    // Packed -2x coefficients for this thread's 4 queries (12 regs).
    unsigned long long nx0p[QPT], nx1p[QPT], nx2p[QPT];
    #pragma unroll
    for (int qy = 0; qy < QPT; ++qy) {
        const int qi = qbase + qy * GSZ + lid;
        const float* qp = qset + ((size_t)b * NPTS + qi) * 3;
        nx0p[qy] = pack2(-2.0f * qp[0]);
        nx1p[qy] = pack2(-2.0f * qp[1]);
        nx2p[qy] = pack2(-2.0f * qp[2]);
    }

    // Paired-target records (32 B each):
    //   s_t[2r]   = (y0a, y0b, y1a, y1b)
    //   s_t[2r+1] = (y2a, y2b, |ya|^2, |yb|^2)
    __shared__ float4 s_t[2 * RECS];        // 16 KB, reused for merges

    {
        const float2* tb2 = (const float2*)(tset + ((size_t)b * NPTS + ts * TILE) * 3);
        for (int i = tid; i < RECS; i += TPB) {
            float2 e0 = tb2[3 * i + 0];     // (a0, a1)
            float2 e1 = tb2[3 * i + 1];     // (a2, b0)
            float2 e2 = tb2[3 * i + 2];     // (b1, b2)
            float na = fmaf(e0.x, e0.x, fmaf(e0.y, e0.y, e1.x * e1.x));
            float nb = fmaf(e1.y, e1.y, fmaf(e2.x, e2.x, e2.y * e2.y));
            s_t[2 * i]     = make_float4(e0.x, e1.y, e0.y, e2.x);
            s_t[2 * i + 1] = make_float4(e1.x, e2.y, na,   nb);
        }
    }
    __syncthreads();

    float mn0[QPT], mn1[QPT];
    #pragma unroll
    for (int qy = 0; qy < QPT; ++qy) { mn0[qy] = 3.402823466e38f; mn1[qy] = 3.402823466e38f; }

    // Group g scans records [g*RPG, (g+1)*RPG).
    {
        const ulonglong2* sp = (const ulonglong2*)s_t + (size_t)(2 * g * RPG);
        #pragma unroll 4
        for (int r = 0; r < RPG; ++r) {
            const ulonglong2 p = sp[2 * r];      // y0-pair, y1-pair
            const ulonglong2 q = sp[2 * r + 1];  // y2-pair, norm-pair
            #pragma unroll
            for (int qy = 0; qy < QPT; ++qy) {
                unsigned long long d;
                asm("fma.rn.f32x2 %0, %1, %2, %3;" : "=l"(d) : "l"(nx2p[qy]), "l"(q.x), "l"(q.y));
                asm("fma.rn.f32x2 %0, %1, %2, %3;" : "=l"(d) : "l"(nx1p[qy]), "l"(p.y), "l"(d));
                asm("fma.rn.f32x2 %0, %1, %2, %3;" : "=l"(d) : "l"(nx0p[qy]), "l"(p.x), "l"(d));
                float dlo, dhi;
                asm("mov.b64 {%0, %1}, %2;" : "=f"(dlo), "=f"(dhi) : "l"(d));
                mn0[qy] = fminf(mn0[qy], dlo);
                mn1[qy] = fminf(mn1[qy], dhi);
            }
        }
    }

    // ---- In-block merge across the 4 groups (reuse s_t). ----
    __syncthreads();
    float* s_mn  = (float*)s_t;              // [NGRP][QPB]
    float* s_red = (float*)s_t + NGRP * QPB; // [TPB]
    #pragma unroll
    for (int qy = 0; qy < QPT; ++qy)
        s_mn[g * QPB + qy * GSZ + lid] = fminf(mn0[qy], mn1[qy]);
    __syncthreads();

    float mnf = s_mn[tid];
    #pragma unroll
    for (int gg = 1; gg < NGRP; ++gg)
        mnf = fminf(mnf, s_mn[gg * QPB + tid]);

    // Publish this slice's raw mins; elect the last-arriving slice block.
    const int gid = (dir * B_DIM + b) * QBLK + blockIdx.x;   // 0..255
    g_min[(gid * TSPLIT + ts) * QPB + tid] = mnf;

    __shared__ int s_lastSlice;
    __syncthreads();
    if (tid == 0) {
        __threadfence();
        unsigned int old = atomicInc(&g_cnt1[gid], TSPLIT - 1);  // wraps -> reset
        s_lastSlice = (old == TSPLIT - 1);
    }
    __syncthreads();
    if (!s_lastSlice) return;

    // ---- Cross-slice merge + clamp + block partial sum. ----
    {
        const volatile float* vm = g_min + (size_t)gid * TSPLIT * QPB;
        float m = vm[tid];
        #pragma unroll
        for (int t = 1; t < TSPLIT; ++t)
            m = fminf(m, vm[t * QPB + tid]);

        const float* qp = qset + ((size_t)b * NPTS + qbase + tid) * 3;
        const float x0 = qp[0], x1 = qp[1], x2 = qp[2];
        const float xn = fmaf(x0, x0, fmaf(x1, x1, x2 * x2));
        float sq = fmaxf(m + xn, 0.0f) * (1.0f / (float)(B_DIM * NPTS));

        s_red[tid] = sq;
        __syncthreads();
        #pragma unroll
        for (int s = TPB / 2; s > 0; s >>= 1) {
            if (tid < s) s_red[tid] += s_red[tid + s];
            __syncthreads();
        }
    }

    __shared__ int s_lastGroup;
    if (tid == 0) {
        g_partials[gid] = s_red[0];
        __threadfence();
        unsigned int old = atomicInc(&g_cnt2, NGROUPS - 1);  // wraps -> reset
        s_lastGroup = (old == NGROUPS - 1);
    }
    __syncthreads();
    if (!s_lastGroup) return;

    // ---- Final fixed-order sum over the 256 group partials. ----
    {
        const volatile float* vp = g_partials;
        s_red[tid] = vp[tid];                 // NGROUPS == TPB == 256
        __syncthreads();
        #pragma unroll
        for (int s = TPB / 2; s > 0; s >>= 1) {
            if (tid < s) s_red[tid] += s_red[tid + s];
            __syncthreads();
        }
        if (tid == 0) out[0] = s_red[0];
    }
}

extern "C" void kernel_launch(void* const* d_in, const int* in_sizes, int n_in,
                              void* d_out, int out_size)
{
    const float* in_pts = (const float*)d_in[0];   // [8, 4096, 3]
    const float* tg_pts = (const float*)d_in[1];   // [8, 4096, 3]
    float* out = (float*)d_out;

    dim3 grid(QBLK, B_DIM, GRIDZ);
    chamfer_fused_kernel<<<grid, TPB>>>(in_pts, tg_pts, out);
}